// round 1
// baseline (speedup 1.0000x reference)
#include <cuda_runtime.h>
#include <cuda_bf16.h>

// Problem constants (fixed by the reference)
#define N_USERS   100000
#define N_ITEMS   50000
#define FDIM      64
#define N_LAYERS  3

#define NUF (N_USERS * FDIM)   // 6,400,000 floats
#define NIF (N_ITEMS * FDIM)   // 3,200,000 floats

// Scratch: per-layer embeddings, layers 0..3
__device__ float g_u[N_LAYERS + 1][NUF];   // 102.4 MB
__device__ float g_i[N_LAYERS + 1][NIF];   //  51.2 MB

// ---------------------------------------------------------------------------
// Kernel 1: copy layer-0 embeddings into scratch (vectorized float4)
// ---------------------------------------------------------------------------
__global__ void k_copy0(const float4* __restrict__ emb_u,
                        const float4* __restrict__ emb_i,
                        int nuf4, int nif4) {
    int t = blockIdx.x * blockDim.x + threadIdx.x;
    if (t < nuf4) reinterpret_cast<float4*>(g_u[0])[t] = emb_u[t];
    if (t < nif4) reinterpret_cast<float4*>(g_i[0])[t] = emb_i[t];
}

// ---------------------------------------------------------------------------
// Kernel 2: per-layer init of accumulators with the diagonal term:
//   u_k = u_{k-1} * d_users ,  i_k = i_{k-1} * d_items
// Indexed in float4 units; d is per-row (64 floats = 16 float4 per row).
// ---------------------------------------------------------------------------
__global__ void k_scale_init(const float* __restrict__ du,
                             const float* __restrict__ di,
                             int k, int nuf4, int nif4) {
    int t = blockIdx.x * blockDim.x + threadIdx.x;
    if (t < nuf4) {
        float4 v = reinterpret_cast<const float4*>(g_u[k - 1])[t];
        float d = du[t >> 4];
        v.x *= d; v.y *= d; v.z *= d; v.w *= d;
        reinterpret_cast<float4*>(g_u[k])[t] = v;
    } else {
        int s = t - nuf4;
        if (s < nif4) {
            float4 v = reinterpret_cast<const float4*>(g_i[k - 1])[s];
            float d = di[s >> 4];
            v.x *= d; v.y *= d; v.z *= d; v.w *= d;
            reinterpret_cast<float4*>(g_i[k])[s] = v;
        }
    }
}

// ---------------------------------------------------------------------------
// Kernel 3: fused dual SpMM for layer k (both directions are independent):
//   u_k += sum_e vals_ui[e] * i_{k-1}[edge_item[e]]  scattered to edge_user[e]
//   i_k += sum_e vals_iu[e] * u_{k-1}[edge_user[e]]  scattered to edge_item[e]
// 16 threads per edge; each thread handles one float4 (gather + red.v4.f32).
// Slots [0, ne*16) are the u<-i direction; [ne*16, 2*ne*16) are i<-u.
// ---------------------------------------------------------------------------
__global__ void k_spmm(const int* __restrict__ edge_user,
                       const int* __restrict__ edge_item,
                       const float* __restrict__ vals_ui,
                       const float* __restrict__ vals_iu,
                       int ne, int k) {
    long long s = (long long)blockIdx.x * blockDim.x + threadIdx.x;
    long long half = (long long)ne * 16;
    if (s >= 2 * half) return;

    int sub = (int)(s & 15);
    const float* __restrict__ src;
    float* dst;
    int srow, drow;
    float v;

    if (s < half) {
        int e = (int)(s >> 4);
        srow = edge_item[e];
        drow = edge_user[e];
        v    = vals_ui[e];
        src  = g_i[k - 1];
        dst  = g_u[k];
    } else {
        int e = (int)((s - half) >> 4);
        srow = edge_user[e];
        drow = edge_item[e];
        v    = vals_iu[e];
        src  = g_u[k - 1];
        dst  = g_i[k];
    }

    float4 x = *reinterpret_cast<const float4*>(src + (long long)srow * FDIM + sub * 4);
    x.x *= v; x.y *= v; x.z *= v; x.w *= v;

    float* p = dst + (long long)drow * FDIM + sub * 4;
    asm volatile("red.global.add.v4.f32 [%0], {%1, %2, %3, %4};"
                 :: "l"(p), "f"(x.x), "f"(x.y), "f"(x.z), "f"(x.w)
                 : "memory");
}

// ---------------------------------------------------------------------------
// Kernel 4: output gather.
// out layout: [seg(3)][batch][256], seg 0 = users (from g_u), 1 = pos_item,
// 2 = neg_item (from g_i). Row feature f = k*64 + j comes from layer-k table.
// Thread per float4: t = seg*batch*64 + b*64 + q, q = k*16 + f4.
// ---------------------------------------------------------------------------
__global__ void k_out_gather(const int* __restrict__ users,
                             const int* __restrict__ pos_item,
                             const int* __restrict__ neg_item,
                             float4* __restrict__ out, int batch) {
    int t = blockIdx.x * blockDim.x + threadIdx.x;
    int total = 3 * batch * 64;
    if (t >= total) return;

    int q   = t & 63;
    int b   = (t >> 6) % batch;
    int seg = t / (batch * 64);
    int k   = q >> 4;
    int f4  = q & 15;

    int row;
    const float* tab;
    if (seg == 0)      { row = users[b];    tab = g_u[k]; }
    else if (seg == 1) { row = pos_item[b]; tab = g_i[k]; }
    else               { row = neg_item[b]; tab = g_i[k]; }

    out[t] = *reinterpret_cast<const float4*>(tab + (long long)row * FDIM + f4 * 4);
}

// ---------------------------------------------------------------------------
// kernel_launch: 8 launches on the default stream (stream order = layer sync)
// ---------------------------------------------------------------------------
extern "C" void kernel_launch(void* const* d_in, const int* in_sizes, int n_in,
                              void* d_out, int out_size) {
    const int*   edge_user = (const int*)  d_in[0];
    const int*   edge_item = (const int*)  d_in[1];
    const float* vals_ui   = (const float*)d_in[2];
    const float* vals_iu   = (const float*)d_in[3];
    const float* d_users   = (const float*)d_in[4];
    const float* d_items   = (const float*)d_in[5];
    const float* emb_user  = (const float*)d_in[6];
    const float* emb_item  = (const float*)d_in[7];
    const int*   users     = (const int*)  d_in[8];
    const int*   pos_item  = (const int*)  d_in[9];
    const int*   neg_item  = (const int*)  d_in[10];

    const int ne    = in_sizes[0];
    const int nuf   = in_sizes[6];          // N_USERS * 64
    const int nif   = in_sizes[7];          // N_ITEMS * 64
    const int batch = in_sizes[8];
    const int nuf4  = nuf / 4;
    const int nif4  = nif / 4;

    const int TPB = 256;

    // Layer 0 copy
    {
        int n = (nuf4 > nif4 ? nuf4 : nif4);
        k_copy0<<<(n + TPB - 1) / TPB, TPB>>>(
            (const float4*)emb_user, (const float4*)emb_item, nuf4, nif4);
    }

    // Layers 1..3
    long long spmm_slots = 2LL * ne * 16;
    int spmm_blocks = (int)((spmm_slots + TPB - 1) / TPB);
    int init_n = nuf4 + nif4;
    int init_blocks = (init_n + TPB - 1) / TPB;

    for (int k = 1; k <= N_LAYERS; k++) {
        k_scale_init<<<init_blocks, TPB>>>(d_users, d_items, k, nuf4, nif4);
        k_spmm<<<spmm_blocks, TPB>>>(edge_user, edge_item, vals_ui, vals_iu, ne, k);
    }

    // Output gather
    {
        int total = 3 * batch * 64;
        k_out_gather<<<(total + TPB - 1) / TPB, TPB>>>(
            users, pos_item, neg_item, (float4*)d_out, batch);
    }
}

// round 3
// speedup vs baseline: 1.9806x; 1.9806x over previous
#include <cuda_runtime.h>
#include <cuda_bf16.h>

// Problem constants (fixed by the reference)
#define N_USERS   100000
#define N_ITEMS   50000
#define FDIM      64
#define N_LAYERS  3
#define N_EDGES_MAX 3200000

#define NUF (N_USERS * FDIM)   // 6,400,000 floats
#define NIF (N_ITEMS * FDIM)   // 3,200,000 floats

// ---------------------------------------------------------------------------
// Device scratch (static globals; no runtime allocation)
// ---------------------------------------------------------------------------
__device__ float g_u[N_LAYERS][NUF];          // layers 1..3 user embeddings (76.8 MB)
__device__ float g_i[N_LAYERS][NIF];          // layers 1..3 item embeddings (38.4 MB)

__device__ int2  g_csr_ui[N_EDGES_MAX];       // (item_col, val bits) keyed by user
__device__ int2  g_csr_iu[N_EDGES_MAX];       // (user_col, val bits) keyed by item

__device__ int   g_ptr_u[N_USERS + 1];
__device__ int   g_ptr_i[N_ITEMS + 1];
__device__ int   g_next_u[N_USERS];
__device__ int   g_next_i[N_ITEMS];
__device__ int   g_aux_u[128];
__device__ int   g_aux_i[128];

// ---------------------------------------------------------------------------
// CSR build pipeline
// ---------------------------------------------------------------------------
__global__ void k_zero_ptrs() {
    int t = blockIdx.x * blockDim.x + threadIdx.x;
    if (t <= N_USERS) g_ptr_u[t] = 0;
    if (t <= N_ITEMS) g_ptr_i[t] = 0;
}

__global__ void k_hist(const int* __restrict__ edge_user,
                       const int* __restrict__ edge_item, int ne) {
    int t = blockIdx.x * blockDim.x + threadIdx.x;
    if (t >= ne) return;
    atomicAdd(&g_ptr_u[edge_user[t]], 1);
    atomicAdd(&g_ptr_i[edge_item[t]], 1);
}

// Block-level exclusive scan (1024-wide Hillis-Steele); writes block totals.
__global__ void k_scan1(int* __restrict__ a, int n, int* __restrict__ aux) {
    __shared__ int s[1024];
    int i = blockIdx.x * 1024 + threadIdx.x;
    int v = (i < n) ? a[i] : 0;
    s[threadIdx.x] = v;
    __syncthreads();
    #pragma unroll
    for (int off = 1; off < 1024; off <<= 1) {
        int t = (threadIdx.x >= off) ? s[threadIdx.x - off] : 0;
        __syncthreads();
        s[threadIdx.x] += t;
        __syncthreads();
    }
    int incl = s[threadIdx.x];
    if (i < n) a[i] = incl - v;                 // exclusive
    if (threadIdx.x == 1023) aux[blockIdx.x] = incl;
}

// Single-block exclusive scan of block totals (n <= 128).
__global__ void k_scan2(int* __restrict__ aux, int n) {
    __shared__ int s[128];
    int v = (threadIdx.x < n) ? aux[threadIdx.x] : 0;
    s[threadIdx.x] = v;
    __syncthreads();
    #pragma unroll
    for (int off = 1; off < 128; off <<= 1) {
        int t = (threadIdx.x >= off) ? s[threadIdx.x - off] : 0;
        __syncthreads();
        s[threadIdx.x] += t;
        __syncthreads();
    }
    if (threadIdx.x < n) aux[threadIdx.x] = s[threadIdx.x] - v;
}

// Add block offsets; produce final exclusive row_ptr and mutable cursor copy.
__global__ void k_scan3(int* __restrict__ a, int n, const int* __restrict__ aux,
                        int* __restrict__ next, int total) {
    int i = blockIdx.x * 1024 + threadIdx.x;
    if (i < n) {
        int v = a[i] + aux[blockIdx.x];
        a[i] = v;
        next[i] = v;
    }
    if (i == 0) a[n] = total;
}

// Scatter edges into both CSR structures.
__global__ void k_build(const int* __restrict__ edge_user,
                        const int* __restrict__ edge_item,
                        const float* __restrict__ vals_ui,
                        const float* __restrict__ vals_iu, int ne) {
    int t = blockIdx.x * blockDim.x + threadIdx.x;
    if (t >= ne) return;
    int u = edge_user[t];
    int i = edge_item[t];
    int pu = atomicAdd(&g_next_u[u], 1);
    g_csr_ui[pu] = make_int2(i, __float_as_int(vals_ui[t]));
    int pi = atomicAdd(&g_next_i[i], 1);
    g_csr_iu[pi] = make_int2(u, __float_as_int(vals_iu[t]));
}

// ---------------------------------------------------------------------------
// CSR SpMM, one warp per destination row, both directions in one grid.
//   rows [0, nu):        u_out[r] = sum vals_ui * i_prev[col] + u_prev[r]*du[r]
//   rows [nu, nu+ni):    i_out[r] = sum vals_iu * u_prev[col] + i_prev[r]*di[r]
// Each lane owns 2 consecutive floats of the 64-wide row (float2).
// ---------------------------------------------------------------------------
__global__ void k_spmm_csr(const float* __restrict__ u_prev,
                           const float* __restrict__ i_prev,
                           const float* __restrict__ du,
                           const float* __restrict__ di,
                           float* __restrict__ u_out,
                           float* __restrict__ i_out) {
    __shared__ int2 stage[8][32];
    int warp = threadIdx.x >> 5;
    int lane = threadIdx.x & 31;
    int row = blockIdx.x * 8 + warp;

    const int2* csr; const int* ptr;
    const float* src; const float* prev; const float* dvec;
    float* dst; int r;

    if (row < N_USERS) {
        r = row; csr = g_csr_ui; ptr = g_ptr_u;
        src = i_prev; prev = u_prev; dvec = du; dst = u_out;
    } else {
        r = row - N_USERS;
        if (r >= N_ITEMS) return;
        csr = g_csr_iu; ptr = g_ptr_i;
        src = u_prev; prev = i_prev; dvec = di; dst = i_out;
    }

    int beg = ptr[r];
    int end = ptr[r + 1];
    float accx = 0.f, accy = 0.f;

    for (int b = beg; b < end; b += 32) {
        int n = min(32, end - b);
        if (lane < n) stage[warp][lane] = csr[b + lane];
        __syncwarp();
        #pragma unroll 4
        for (int j = 0; j < n; j++) {
            int2 p = stage[warp][j];
            float2 x = *(const float2*)(src + (size_t)p.x * FDIM + lane * 2);
            float w = __int_as_float(p.y);
            accx = fmaf(w, x.x, accx);
            accy = fmaf(w, x.y, accy);
        }
        __syncwarp();
    }

    float dd = dvec[r];
    float2 pv = *(const float2*)(prev + (size_t)r * FDIM + lane * 2);
    accx = fmaf(dd, pv.x, accx);
    accy = fmaf(dd, pv.y, accy);
    *(float2*)(dst + (size_t)r * FDIM + lane * 2) = make_float2(accx, accy);
}

// ---------------------------------------------------------------------------
// Output gather: out layout [seg(3)][batch][256].
// Feature q (in float4 units, q=0..63): layer k = q>>4, within-row f4 = q&15.
// Layer 0 reads from the input embedding tensors directly.
// ---------------------------------------------------------------------------
__global__ void k_out_gather(const int* __restrict__ users,
                             const int* __restrict__ pos_item,
                             const int* __restrict__ neg_item,
                             const float* __restrict__ emb_user,
                             const float* __restrict__ emb_item,
                             float4* __restrict__ out, int batch) {
    int t = blockIdx.x * blockDim.x + threadIdx.x;
    int total = 3 * batch * 64;
    if (t >= total) return;

    int q   = t & 63;
    int b   = (t >> 6) % batch;
    int seg = t / (batch * 64);
    int k   = q >> 4;
    int f4  = q & 15;

    int row;
    const float* tab;
    if (seg == 0) {
        row = users[b];
        tab = (k == 0) ? emb_user : g_u[k - 1];
    } else {
        row = (seg == 1) ? pos_item[b] : neg_item[b];
        tab = (k == 0) ? emb_item : g_i[k - 1];
    }
    out[t] = *(const float4*)(tab + (size_t)row * FDIM + f4 * 4);
}

// ---------------------------------------------------------------------------
// kernel_launch
// ---------------------------------------------------------------------------
extern "C" void kernel_launch(void* const* d_in, const int* in_sizes, int n_in,
                              void* d_out, int out_size) {
    const int*   edge_user = (const int*)  d_in[0];
    const int*   edge_item = (const int*)  d_in[1];
    const float* vals_ui   = (const float*)d_in[2];
    const float* vals_iu   = (const float*)d_in[3];
    const float* d_users   = (const float*)d_in[4];
    const float* d_items   = (const float*)d_in[5];
    const float* emb_user  = (const float*)d_in[6];
    const float* emb_item  = (const float*)d_in[7];
    const int*   users     = (const int*)  d_in[8];
    const int*   pos_item  = (const int*)  d_in[9];
    const int*   neg_item  = (const int*)  d_in[10];

    const int ne    = in_sizes[0];
    const int batch = in_sizes[8];
    const int TPB   = 256;

    // Resolve device-global addresses host-side for scan kernels
    int* ptr_u;  int* ptr_i;  int* next_u; int* next_i; int* aux_u; int* aux_i;
    cudaGetSymbolAddress((void**)&ptr_u,  g_ptr_u);
    cudaGetSymbolAddress((void**)&ptr_i,  g_ptr_i);
    cudaGetSymbolAddress((void**)&next_u, g_next_u);
    cudaGetSymbolAddress((void**)&next_i, g_next_i);
    cudaGetSymbolAddress((void**)&aux_u,  g_aux_u);
    cudaGetSymbolAddress((void**)&aux_i,  g_aux_i);

    float* gu[N_LAYERS]; float* gi[N_LAYERS];
    {
        float* base_u; float* base_i;
        cudaGetSymbolAddress((void**)&base_u, g_u);
        cudaGetSymbolAddress((void**)&base_i, g_i);
        for (int k = 0; k < N_LAYERS; k++) {
            gu[k] = base_u + (size_t)k * NUF;
            gi[k] = base_i + (size_t)k * NIF;
        }
    }

    // --- CSR build ---
    k_zero_ptrs<<<(N_USERS + 1 + TPB - 1) / TPB, TPB>>>();
    k_hist<<<(ne + TPB - 1) / TPB, TPB>>>(edge_user, edge_item, ne);

    int nb_u = (N_USERS + 1023) / 1024;
    int nb_i = (N_ITEMS + 1023) / 1024;
    k_scan1<<<nb_u, 1024>>>(ptr_u, N_USERS, aux_u);
    k_scan1<<<nb_i, 1024>>>(ptr_i, N_ITEMS, aux_i);
    k_scan2<<<1, 128>>>(aux_u, nb_u);
    k_scan2<<<1, 128>>>(aux_i, nb_i);
    k_scan3<<<nb_u, 1024>>>(ptr_u, N_USERS, aux_u, next_u, ne);
    k_scan3<<<nb_i, 1024>>>(ptr_i, N_ITEMS, aux_i, next_i, ne);

    k_build<<<(ne + TPB - 1) / TPB, TPB>>>(edge_user, edge_item, vals_ui, vals_iu, ne);

    // --- 3 layers of fused SpMM + diagonal ---
    int spmm_blocks = (N_USERS + N_ITEMS + 7) / 8;
    for (int k = 1; k <= N_LAYERS; k++) {
        const float* up = (k == 1) ? emb_user : gu[k - 2];
        const float* ip = (k == 1) ? emb_item : gi[k - 2];
        k_spmm_csr<<<spmm_blocks, TPB>>>(up, ip, d_users, d_items,
                                         gu[k - 1], gi[k - 1]);
    }

    // --- Output gather ---
    int total = 3 * batch * 64;
    k_out_gather<<<(total + TPB - 1) / TPB, TPB>>>(
        users, pos_item, neg_item, emb_user, emb_item, (float4*)d_out, batch);
}

// round 4
// speedup vs baseline: 2.0671x; 1.0436x over previous
#include <cuda_runtime.h>
#include <cuda_fp16.h>

// Problem constants (fixed by the reference)
#define N_USERS   100000
#define N_ITEMS   50000
#define FDIM      64
#define N_LAYERS  3
#define NE_MAX    3200000

#define NUF (N_USERS * FDIM)   // 6,400,000
#define NIF (N_ITEMS * FDIM)   // 3,200,000
#define NB_U ((N_USERS + 1023) / 1024)   // 98
#define NB_I ((N_ITEMS + 1023) / 1024)   // 49

// ---------------------------------------------------------------------------
// Device scratch (static globals; no runtime allocation)
// fp16 embedding tables: [0] = converted inputs, [1..3] = layer outputs.
// ---------------------------------------------------------------------------
__device__ __half g_u16[N_LAYERS + 1][NUF];   // 51.2 MB
__device__ __half g_i16[N_LAYERS + 1][NIF];   // 25.6 MB

__device__ int2  g_csr_ui[NE_MAX];            // (item_col, val bits) keyed by user
__device__ int2  g_csr_iu[NE_MAX];            // (user_col, val bits) keyed by item

__device__ int   g_ptr_u[N_USERS + 1];
__device__ int   g_ptr_i[N_ITEMS + 1];
__device__ int   g_next_u[N_USERS];
__device__ int   g_next_i[N_ITEMS];
__device__ int   g_aux_u[128];
__device__ int   g_aux_i[128];

// ---------------------------------------------------------------------------
// Kernel 1: fused init — convert input embeddings fp32 -> fp16 tables (layer 0)
// and zero the histogram pointer arrays. Thread roles by index range.
// ---------------------------------------------------------------------------
__global__ void k_init(const float4* __restrict__ emb_u,
                       const float4* __restrict__ emb_i) {
    const int nuf4 = NUF / 4;
    const int nif4 = NIF / 4;
    int t = blockIdx.x * blockDim.x + threadIdx.x;

    if (t < nuf4) {
        float4 v = emb_u[t];
        __half2* p = reinterpret_cast<__half2*>(g_u16[0]);
        p[2 * t]     = __floats2half2_rn(v.x, v.y);
        p[2 * t + 1] = __floats2half2_rn(v.z, v.w);
        return;
    }
    t -= nuf4;
    if (t < nif4) {
        float4 v = emb_i[t];
        __half2* p = reinterpret_cast<__half2*>(g_i16[0]);
        p[2 * t]     = __floats2half2_rn(v.x, v.y);
        p[2 * t + 1] = __floats2half2_rn(v.z, v.w);
        return;
    }
    t -= nif4;
    if (t <= N_USERS) { g_ptr_u[t] = 0; return; }
    t -= (N_USERS + 1);
    if (t <= N_ITEMS) { g_ptr_i[t] = 0; }
}

// ---------------------------------------------------------------------------
// Kernel 2: degree histogram
// ---------------------------------------------------------------------------
__global__ void k_hist(const int* __restrict__ edge_user,
                       const int* __restrict__ edge_item, int ne) {
    int t = blockIdx.x * blockDim.x + threadIdx.x;
    if (t >= ne) return;
    atomicAdd(&g_ptr_u[edge_user[t]], 1);
    atomicAdd(&g_ptr_i[edge_item[t]], 1);
}

// ---------------------------------------------------------------------------
// Kernel 3: fused block-level exclusive scan (u blocks then i blocks)
// ---------------------------------------------------------------------------
__global__ void k_scan1() {
    __shared__ int s[1024];
    int b = blockIdx.x;
    int* a; int n; int* aux; int boff;
    if (b < NB_U) { a = g_ptr_u; n = N_USERS; aux = g_aux_u; boff = b; }
    else          { a = g_ptr_i; n = N_ITEMS; aux = g_aux_i; boff = b - NB_U; }

    int i = boff * 1024 + threadIdx.x;
    int v = (i < n) ? a[i] : 0;
    s[threadIdx.x] = v;
    __syncthreads();
    #pragma unroll
    for (int off = 1; off < 1024; off <<= 1) {
        int t = (threadIdx.x >= off) ? s[threadIdx.x - off] : 0;
        __syncthreads();
        s[threadIdx.x] += t;
        __syncthreads();
    }
    int incl = s[threadIdx.x];
    if (i < n) a[i] = incl - v;                 // exclusive
    if (threadIdx.x == 1023) aux[boff] = incl;
}

// ---------------------------------------------------------------------------
// Kernel 4: fused scan of block totals (block 0 -> aux_u, block 1 -> aux_i)
// ---------------------------------------------------------------------------
__global__ void k_scan2() {
    __shared__ int s[128];
    int* aux = (blockIdx.x == 0) ? g_aux_u : g_aux_i;
    int n    = (blockIdx.x == 0) ? NB_U : NB_I;
    int v = (threadIdx.x < n) ? aux[threadIdx.x] : 0;
    s[threadIdx.x] = v;
    __syncthreads();
    #pragma unroll
    for (int off = 1; off < 128; off <<= 1) {
        int t = (threadIdx.x >= off) ? s[threadIdx.x - off] : 0;
        __syncthreads();
        s[threadIdx.x] += t;
        __syncthreads();
    }
    if (threadIdx.x < n) aux[threadIdx.x] = s[threadIdx.x] - v;
}

// ---------------------------------------------------------------------------
// Kernel 5: fused finalize — add block offsets, emit row_ptr + cursor copy
// ---------------------------------------------------------------------------
__global__ void k_scan3(int ne) {
    int b = blockIdx.x;
    int* a; int n; const int* aux; int* next; int boff;
    if (b < NB_U) { a = g_ptr_u; n = N_USERS; aux = g_aux_u; next = g_next_u; boff = b; }
    else          { a = g_ptr_i; n = N_ITEMS; aux = g_aux_i; next = g_next_i; boff = b - NB_U; }

    int i = boff * 1024 + threadIdx.x;
    if (i < n) {
        int v = a[i] + aux[boff];
        a[i] = v;
        next[i] = v;
    }
    if (i == 0) a[n] = ne;
}

// ---------------------------------------------------------------------------
// Kernel 6: scatter edges into both CSR structures
// ---------------------------------------------------------------------------
__global__ void k_build(const int* __restrict__ edge_user,
                        const int* __restrict__ edge_item,
                        const float* __restrict__ vals_ui,
                        const float* __restrict__ vals_iu, int ne) {
    int t = blockIdx.x * blockDim.x + threadIdx.x;
    if (t >= ne) return;
    int u = edge_user[t];
    int i = edge_item[t];
    int pu = atomicAdd(&g_next_u[u], 1);
    g_csr_ui[pu] = make_int2(i, __float_as_int(vals_ui[t]));
    int pi = atomicAdd(&g_next_i[i], 1);
    g_csr_iu[pi] = make_int2(u, __float_as_int(vals_iu[t]));
}

// ---------------------------------------------------------------------------
// Kernel 7: CSR SpMM (fp16 tables, fp32 accumulate), one warp per dest row.
//   rows [0, NU):      u_k[r] = sum vals_ui * i_{k-1}[col] + u_{k-1}[r]*du[r]
//   rows [NU, NU+NI):  i_k[r] = sum vals_iu * u_{k-1}[col] + i_{k-1}[r]*di[r]
// Each lane owns one half2 (2 floats) of the 64-wide row. Row = 128 bytes.
// ---------------------------------------------------------------------------
__global__ void k_spmm(const float* __restrict__ du,
                       const float* __restrict__ di, int k) {
    __shared__ int2 stage[8][32];
    int warp = threadIdx.x >> 5;
    int lane = threadIdx.x & 31;
    int row = blockIdx.x * 8 + warp;

    const int2* csr; const int* ptr;
    const __half2* src; const __half2* prev; const float* dvec;
    __half2* dst; int r;

    if (row < N_USERS) {
        r = row; csr = g_csr_ui; ptr = g_ptr_u;
        src  = reinterpret_cast<const __half2*>(g_i16[k - 1]);
        prev = reinterpret_cast<const __half2*>(g_u16[k - 1]);
        dvec = du;
        dst  = reinterpret_cast<__half2*>(g_u16[k]);
    } else {
        r = row - N_USERS;
        if (r >= N_ITEMS) return;
        csr = g_csr_iu; ptr = g_ptr_i;
        src  = reinterpret_cast<const __half2*>(g_u16[k - 1]);
        prev = reinterpret_cast<const __half2*>(g_i16[k - 1]);
        dvec = di;
        dst  = reinterpret_cast<__half2*>(g_i16[k]);
    }

    int beg = ptr[r];
    int end = ptr[r + 1];
    float accx = 0.f, accy = 0.f;

    for (int b = beg; b < end; b += 32) {
        int n = min(32, end - b);
        if (lane < n) stage[warp][lane] = csr[b + lane];
        __syncwarp();
        #pragma unroll 4
        for (int j = 0; j < n; j++) {
            int2 p = stage[warp][j];
            float2 x = __half22float2(src[p.x * 32 + lane]);
            float w = __int_as_float(p.y);
            accx = fmaf(w, x.x, accx);
            accy = fmaf(w, x.y, accy);
        }
        __syncwarp();
    }

    float dd = dvec[r];
    float2 pv = __half22float2(prev[r * 32 + lane]);
    accx = fmaf(dd, pv.x, accx);
    accy = fmaf(dd, pv.y, accy);
    dst[r * 32 + lane] = __floats2half2_rn(accx, accy);
}

// ---------------------------------------------------------------------------
// Kernel 8: output gather. out layout [seg(3)][batch][256], fp32.
// Feature q (float4 units, q=0..63): layer k = q>>4, within-row f4 = q&15.
// Layer 0 reads the original fp32 inputs; layers 1..3 read fp16 tables.
// ---------------------------------------------------------------------------
__global__ void k_out_gather(const int* __restrict__ users,
                             const int* __restrict__ pos_item,
                             const int* __restrict__ neg_item,
                             const float* __restrict__ emb_user,
                             const float* __restrict__ emb_item,
                             float4* __restrict__ out, int batch) {
    int t = blockIdx.x * blockDim.x + threadIdx.x;
    int total = 3 * batch * 64;
    if (t >= total) return;

    int q   = t & 63;
    int b   = (t >> 6) % batch;
    int seg = t / (batch * 64);
    int k   = q >> 4;
    int f4  = q & 15;

    int row;
    bool is_user = (seg == 0);
    if (is_user)        row = users[b];
    else if (seg == 1)  row = pos_item[b];
    else                row = neg_item[b];

    if (k == 0) {
        const float* tab = is_user ? emb_user : emb_item;
        out[t] = *reinterpret_cast<const float4*>(tab + (size_t)row * FDIM + f4 * 4);
    } else {
        const __half* tab = is_user ? g_u16[k] : g_i16[k];
        uint2 raw = *reinterpret_cast<const uint2*>(tab + (size_t)row * FDIM + f4 * 4);
        __half2 h0 = *reinterpret_cast<const __half2*>(&raw.x);
        __half2 h1 = *reinterpret_cast<const __half2*>(&raw.y);
        float2 a = __half22float2(h0);
        float2 c = __half22float2(h1);
        out[t] = make_float4(a.x, a.y, c.x, c.y);
    }
}

// ---------------------------------------------------------------------------
// kernel_launch: 10 launches on the default stream
// ---------------------------------------------------------------------------
extern "C" void kernel_launch(void* const* d_in, const int* in_sizes, int n_in,
                              void* d_out, int out_size) {
    const int*   edge_user = (const int*)  d_in[0];
    const int*   edge_item = (const int*)  d_in[1];
    const float* vals_ui   = (const float*)d_in[2];
    const float* vals_iu   = (const float*)d_in[3];
    const float* d_users   = (const float*)d_in[4];
    const float* d_items   = (const float*)d_in[5];
    const float* emb_user  = (const float*)d_in[6];
    const float* emb_item  = (const float*)d_in[7];
    const int*   users     = (const int*)  d_in[8];
    const int*   pos_item  = (const int*)  d_in[9];
    const int*   neg_item  = (const int*)  d_in[10];

    const int ne    = in_sizes[0];
    const int batch = in_sizes[8];
    const int TPB   = 256;

    // 1) convert embeddings + zero histograms
    {
        int total = NUF / 4 + NIF / 4 + (N_USERS + 1) + (N_ITEMS + 1);
        k_init<<<(total + TPB - 1) / TPB, TPB>>>(
            (const float4*)emb_user, (const float4*)emb_item);
    }
    // 2-6) CSR build
    k_hist<<<(ne + TPB - 1) / TPB, TPB>>>(edge_user, edge_item, ne);
    k_scan1<<<NB_U + NB_I, 1024>>>();
    k_scan2<<<2, 128>>>();
    k_scan3<<<NB_U + NB_I, 1024>>>(ne);
    k_build<<<(ne + TPB - 1) / TPB, TPB>>>(edge_user, edge_item, vals_ui, vals_iu, ne);

    // 7-9) 3 layers of fused SpMM + diagonal
    int spmm_blocks = (N_USERS + N_ITEMS + 7) / 8;
    for (int k = 1; k <= N_LAYERS; k++) {
        k_spmm<<<spmm_blocks, TPB>>>(d_users, d_items, k);
    }

    // 10) output gather
    int total = 3 * batch * 64;
    k_out_gather<<<(total + TPB - 1) / TPB, TPB>>>(
        users, pos_item, neg_item, emb_user, emb_item, (float4*)d_out, batch);
}

// round 6
// speedup vs baseline: 2.1858x; 1.0574x over previous
#include <cuda_runtime.h>
#include <cuda_fp16.h>

// Problem constants (fixed by the reference)
#define N_USERS   100000
#define N_ITEMS   50000
#define FDIM      64
#define N_LAYERS  3
#define NE_MAX    3200000

#define NUF (N_USERS * FDIM)   // 6,400,000
#define NIF (N_ITEMS * FDIM)   // 3,200,000
#define NTOT (N_USERS + N_ITEMS)
#define SCAN_BLOCKS ((NTOT + 1023) / 1024)   // 147

// ---------------------------------------------------------------------------
// Device scratch (static globals; no runtime allocation)
// ---------------------------------------------------------------------------
__device__ __half g_u16[N_LAYERS + 1][NUF];   // 51.2 MB
__device__ __half g_i16[N_LAYERS + 1][NIF];   // 25.6 MB

__device__ int2  g_csr_ui[NE_MAX];            // (item_col, val bits) keyed by user
__device__ int2  g_csr_iu[NE_MAX];            // (user_col, val bits) keyed by item

__device__ int   g_ptr_u[N_USERS + 1];
__device__ int   g_ptr_i[N_ITEMS + 1];
__device__ int   g_next_u[N_USERS];
__device__ int   g_next_i[N_ITEMS];

// Decoupled-lookback scan state (zeroed each call by k_init)
__device__ unsigned long long g_desc[SCAN_BLOCKS + 1];  // (value<<2) | flag
__device__ int   g_ticket;

// ---------------------------------------------------------------------------
// Kernel 1: fused init — fp32 -> fp16 embedding convert (layer 0 tables),
// zero histograms + scan descriptors + ticket. Thread roles by index range.
// ---------------------------------------------------------------------------
__global__ void k_init(const float4* __restrict__ emb_u,
                       const float4* __restrict__ emb_i) {
    const int nuf4 = NUF / 4;
    const int nif4 = NIF / 4;
    int t = blockIdx.x * blockDim.x + threadIdx.x;

    if (t < nuf4) {
        float4 v = emb_u[t];
        __half2* p = reinterpret_cast<__half2*>(g_u16[0]);
        p[2 * t]     = __floats2half2_rn(v.x, v.y);
        p[2 * t + 1] = __floats2half2_rn(v.z, v.w);
        return;
    }
    t -= nuf4;
    if (t < nif4) {
        float4 v = emb_i[t];
        __half2* p = reinterpret_cast<__half2*>(g_i16[0]);
        p[2 * t]     = __floats2half2_rn(v.x, v.y);
        p[2 * t + 1] = __floats2half2_rn(v.z, v.w);
        return;
    }
    t -= nif4;
    if (t <= N_USERS) { g_ptr_u[t] = 0; return; }
    t -= (N_USERS + 1);
    if (t <= N_ITEMS) { g_ptr_i[t] = 0; return; }
    t -= (N_ITEMS + 1);
    if (t <= SCAN_BLOCKS) { g_desc[t] = 0ULL; return; }
    t -= (SCAN_BLOCKS + 1);
    if (t == 0) g_ticket = 0;
}

// ---------------------------------------------------------------------------
// Kernel 2: degree histogram
// ---------------------------------------------------------------------------
__global__ void k_hist(const int* __restrict__ edge_user,
                       const int* __restrict__ edge_item, int ne) {
    int t = blockIdx.x * blockDim.x + threadIdx.x;
    if (t >= ne) return;
    atomicAdd(&g_ptr_u[edge_user[t]], 1);
    atomicAdd(&g_ptr_i[edge_item[t]], 1);
}

// ---------------------------------------------------------------------------
// Kernel 3: single-pass exclusive scan of the concatenated [u | i] histogram
// via decoupled lookback. Since sum(u-counts) == ne, the i-part is rebased
// by -ne. Also emits the mutable cursor copies and the row_ptr tails.
// 147 blocks <= 148 SMs: entire grid is wave-1 resident, so the spin-wait
// on lower-ticket blocks cannot deadlock.
// ---------------------------------------------------------------------------
__device__ __forceinline__ void desc_store(unsigned long long* p,
                                           unsigned long long v) {
    asm volatile("st.release.gpu.global.u64 [%0], %1;" :: "l"(p), "l"(v) : "memory");
}
__device__ __forceinline__ unsigned long long desc_load(unsigned long long* p) {
    unsigned long long v;
    asm volatile("ld.acquire.gpu.global.u64 %0, [%1];" : "=l"(v) : "l"(p) : "memory");
    return v;
}

__global__ void k_scan(int ne) {
    __shared__ int s[1024];
    __shared__ int s_bid;
    __shared__ int s_prefix;

    if (threadIdx.x == 0) s_bid = atomicAdd(&g_ticket, 1);
    __syncthreads();
    int bid = s_bid;
    int i = bid * 1024 + threadIdx.x;

    int v = 0;
    if (i < N_USERS)    v = g_ptr_u[i];
    else if (i < NTOT)  v = g_ptr_i[i - N_USERS];

    s[threadIdx.x] = v;
    __syncthreads();
    #pragma unroll
    for (int off = 1; off < 1024; off <<= 1) {
        int t = (threadIdx.x >= off) ? s[threadIdx.x - off] : 0;
        __syncthreads();
        s[threadIdx.x] += t;
        __syncthreads();
    }
    int incl = s[threadIdx.x];
    int excl = incl - v;
    int agg  = s[1023];

    if (threadIdx.x == 0) {
        if (bid == 0) {
            desc_store(&g_desc[0], ((unsigned long long)agg << 2) | 2ULL);
            s_prefix = 0;
        } else {
            desc_store(&g_desc[bid], ((unsigned long long)agg << 2) | 1ULL);
            // sequential lookback over lower-ticket blocks
            int prefix = 0;
            int p = bid - 1;
            while (true) {
                unsigned long long d = desc_load(&g_desc[p]);
                if ((d & 3ULL) == 0ULL) { __nanosleep(40); continue; }
                prefix += (int)(d >> 2);
                if ((d & 3ULL) == 2ULL) break;
                p--;
            }
            desc_store(&g_desc[bid],
                       ((unsigned long long)(prefix + agg) << 2) | 2ULL);
            s_prefix = prefix;
        }
    }
    __syncthreads();

    int fin = s_prefix + excl;
    if (i < N_USERS) {
        g_ptr_u[i] = fin;
        g_next_u[i] = fin;
    } else if (i < NTOT) {
        int j = i - N_USERS;
        int w = fin - ne;          // rebase the item part
        g_ptr_i[j] = w;
        g_next_i[j] = w;
    }
    if (i == 0) {
        g_ptr_u[N_USERS] = ne;
        g_ptr_i[N_ITEMS] = ne;
    }
}

// ---------------------------------------------------------------------------
// Kernel 4: scatter edges into both CSR structures
// ---------------------------------------------------------------------------
__global__ void k_build(const int* __restrict__ edge_user,
                        const int* __restrict__ edge_item,
                        const float* __restrict__ vals_ui,
                        const float* __restrict__ vals_iu, int ne) {
    int t = blockIdx.x * blockDim.x + threadIdx.x;
    if (t >= ne) return;
    int u = edge_user[t];
    int i = edge_item[t];
    int pu = atomicAdd(&g_next_u[u], 1);
    g_csr_ui[pu] = make_int2(i, __float_as_int(vals_ui[t]));
    int pi = atomicAdd(&g_next_i[i], 1);
    g_csr_iu[pi] = make_int2(u, __float_as_int(vals_iu[t]));
}

// ---------------------------------------------------------------------------
// Kernel 5: CSR SpMM (fp16 tables, fp32 accumulate), one warp per dest row.
// MLP-optimized inner loop: groups of 8 neighbors, 4 independent accumulator
// pairs so 8 gathers are in flight per warp before any FFMA retires.
// ---------------------------------------------------------------------------
__global__ void __launch_bounds__(256) k_spmm(const float* __restrict__ du,
                                              const float* __restrict__ di,
                                              int k) {
    __shared__ int2 stage[8][32];
    int warp = threadIdx.x >> 5;
    int lane = threadIdx.x & 31;
    int row = blockIdx.x * 8 + warp;

    const int2* csr; const int* ptr;
    const __half2* src; const __half2* prev; const float* dvec;
    __half2* dst; int r;

    if (row < N_USERS) {
        r = row; csr = g_csr_ui; ptr = g_ptr_u;
        src  = reinterpret_cast<const __half2*>(g_i16[k - 1]);
        prev = reinterpret_cast<const __half2*>(g_u16[k - 1]);
        dvec = du;
        dst  = reinterpret_cast<__half2*>(g_u16[k]);
    } else {
        r = row - N_USERS;
        if (r >= N_ITEMS) return;
        csr = g_csr_iu; ptr = g_ptr_i;
        src  = reinterpret_cast<const __half2*>(g_u16[k - 1]);
        prev = reinterpret_cast<const __half2*>(g_i16[k - 1]);
        dvec = di;
        dst  = reinterpret_cast<__half2*>(g_i16[k]);
    }

    int beg = ptr[r];
    int end = ptr[r + 1];

    float ax0 = 0.f, ay0 = 0.f, ax1 = 0.f, ay1 = 0.f;
    float ax2 = 0.f, ay2 = 0.f, ax3 = 0.f, ay3 = 0.f;

    for (int b = beg; b < end; b += 32) {
        int n = min(32, end - b);
        if (lane < n) stage[warp][lane] = csr[b + lane];
        __syncwarp();

        int j = 0;
        for (; j + 8 <= n; j += 8) {
            // Front-batch 8 independent gathers
            int2 p0 = stage[warp][j + 0];
            int2 p1 = stage[warp][j + 1];
            int2 p2 = stage[warp][j + 2];
            int2 p3 = stage[warp][j + 3];
            int2 p4 = stage[warp][j + 4];
            int2 p5 = stage[warp][j + 5];
            int2 p6 = stage[warp][j + 6];
            int2 p7 = stage[warp][j + 7];
            float2 x0 = __half22float2(src[p0.x * 32 + lane]);
            float2 x1 = __half22float2(src[p1.x * 32 + lane]);
            float2 x2 = __half22float2(src[p2.x * 32 + lane]);
            float2 x3 = __half22float2(src[p3.x * 32 + lane]);
            float2 x4 = __half22float2(src[p4.x * 32 + lane]);
            float2 x5 = __half22float2(src[p5.x * 32 + lane]);
            float2 x6 = __half22float2(src[p6.x * 32 + lane]);
            float2 x7 = __half22float2(src[p7.x * 32 + lane]);
            ax0 = fmaf(__int_as_float(p0.y), x0.x, ax0);
            ay0 = fmaf(__int_as_float(p0.y), x0.y, ay0);
            ax1 = fmaf(__int_as_float(p1.y), x1.x, ax1);
            ay1 = fmaf(__int_as_float(p1.y), x1.y, ay1);
            ax2 = fmaf(__int_as_float(p2.y), x2.x, ax2);
            ay2 = fmaf(__int_as_float(p2.y), x2.y, ay2);
            ax3 = fmaf(__int_as_float(p3.y), x3.x, ax3);
            ay3 = fmaf(__int_as_float(p3.y), x3.y, ay3);
            ax0 = fmaf(__int_as_float(p4.y), x4.x, ax0);
            ay0 = fmaf(__int_as_float(p4.y), x4.y, ay0);
            ax1 = fmaf(__int_as_float(p5.y), x5.x, ax1);
            ay1 = fmaf(__int_as_float(p5.y), x5.y, ay1);
            ax2 = fmaf(__int_as_float(p6.y), x6.x, ax2);
            ay2 = fmaf(__int_as_float(p6.y), x6.y, ay2);
            ax3 = fmaf(__int_as_float(p7.y), x7.x, ax3);
            ay3 = fmaf(__int_as_float(p7.y), x7.y, ay3);
        }
        for (; j < n; j++) {
            int2 p = stage[warp][j];
            float2 x = __half22float2(src[p.x * 32 + lane]);
            float w = __int_as_float(p.y);
            ax0 = fmaf(w, x.x, ax0);
            ay0 = fmaf(w, x.y, ay0);
        }
        __syncwarp();
    }

    float accx = (ax0 + ax1) + (ax2 + ax3);
    float accy = (ay0 + ay1) + (ay2 + ay3);

    float dd = dvec[r];
    float2 pv = __half22float2(prev[r * 32 + lane]);
    accx = fmaf(dd, pv.x, accx);
    accy = fmaf(dd, pv.y, accy);
    dst[r * 32 + lane] = __floats2half2_rn(accx, accy);
}

// ---------------------------------------------------------------------------
// Kernel 6: output gather. out layout [seg(3)][batch][256], fp32.
// ---------------------------------------------------------------------------
__global__ void k_out_gather(const int* __restrict__ users,
                             const int* __restrict__ pos_item,
                             const int* __restrict__ neg_item,
                             const float* __restrict__ emb_user,
                             const float* __restrict__ emb_item,
                             float4* __restrict__ out, int batch) {
    int t = blockIdx.x * blockDim.x + threadIdx.x;
    int total = 3 * batch * 64;
    if (t >= total) return;

    int q   = t & 63;
    int b   = (t >> 6) % batch;
    int seg = t / (batch * 64);
    int k   = q >> 4;
    int f4  = q & 15;

    int row;
    bool is_user = (seg == 0);
    if (is_user)        row = users[b];
    else if (seg == 1)  row = pos_item[b];
    else                row = neg_item[b];

    if (k == 0) {
        const float* tab = is_user ? emb_user : emb_item;
        out[t] = *reinterpret_cast<const float4*>(tab + (size_t)row * FDIM + f4 * 4);
    } else {
        const __half* tab = is_user ? g_u16[k] : g_i16[k];
        uint2 raw = *reinterpret_cast<const uint2*>(tab + (size_t)row * FDIM + f4 * 4);
        __half2 h0 = *reinterpret_cast<const __half2*>(&raw.x);
        __half2 h1 = *reinterpret_cast<const __half2*>(&raw.y);
        float2 a = __half22float2(h0);
        float2 c = __half22float2(h1);
        out[t] = make_float4(a.x, a.y, c.x, c.y);
    }
}

// ---------------------------------------------------------------------------
// kernel_launch: 8 launches (ncu -s 5 profiles spmm layer 2)
// ---------------------------------------------------------------------------
extern "C" void kernel_launch(void* const* d_in, const int* in_sizes, int n_in,
                              void* d_out, int out_size) {
    const int*   edge_user = (const int*)  d_in[0];
    const int*   edge_item = (const int*)  d_in[1];
    const float* vals_ui   = (const float*)d_in[2];
    const float* vals_iu   = (const float*)d_in[3];
    const float* d_users   = (const float*)d_in[4];
    const float* d_items   = (const float*)d_in[5];
    const float* emb_user  = (const float*)d_in[6];
    const float* emb_item  = (const float*)d_in[7];
    const int*   users     = (const int*)  d_in[8];
    const int*   pos_item  = (const int*)  d_in[9];
    const int*   neg_item  = (const int*)  d_in[10];

    const int ne    = in_sizes[0];
    const int batch = in_sizes[8];
    const int TPB   = 256;

    // 1) convert embeddings + zero histograms/scan state
    {
        int total = NUF / 4 + NIF / 4 + (N_USERS + 1) + (N_ITEMS + 1)
                  + (SCAN_BLOCKS + 1) + 1;
        k_init<<<(total + TPB - 1) / TPB, TPB>>>(
            (const float4*)emb_user, (const float4*)emb_item);
    }
    // 2) histogram
    k_hist<<<(ne + TPB - 1) / TPB, TPB>>>(edge_user, edge_item, ne);
    // 3) single-pass scan (decoupled lookback)
    k_scan<<<SCAN_BLOCKS, 1024>>>(ne);
    // 4) CSR scatter
    k_build<<<(ne + TPB - 1) / TPB, TPB>>>(edge_user, edge_item, vals_ui, vals_iu, ne);

    // 5-7) 3 layers of fused SpMM + diagonal
    int spmm_blocks = (N_USERS + N_ITEMS + 7) / 8;
    for (int k = 1; k <= N_LAYERS; k++) {
        k_spmm<<<spmm_blocks, TPB>>>(d_users, d_items, k);
    }

    // 8) output gather
    int total = 3 * batch * 64;
    k_out_gather<<<(total + TPB - 1) / TPB, TPB>>>(
        users, pos_item, neg_item, emb_user, emb_item, (float4*)d_out, batch);
}

// round 9
// speedup vs baseline: 2.4376x; 1.1152x over previous
#include <cuda_runtime.h>
#include <cuda_fp16.h>

// Problem constants (fixed by the reference)
#define N_USERS   100000
#define N_ITEMS   50000
#define FDIM      64
#define N_LAYERS  3
#define NE_MAX    3200000

#define NUF (N_USERS * FDIM)   // 6,400,000
#define NIF (N_ITEMS * FDIM)   // 3,200,000
#define NTOT (N_USERS + N_ITEMS)
#define SCAN_BLOCKS ((NTOT + 1023) / 1024)   // 147

// ---------------------------------------------------------------------------
// Device scratch (static globals; no runtime allocation)
// ---------------------------------------------------------------------------
__device__ __half g_u16[N_LAYERS + 1][NUF];   // 51.2 MB
__device__ __half g_i16[N_LAYERS + 1][NIF];   // 25.6 MB

__device__ int2  g_csr_ui[NE_MAX];            // (item_col, val bits) keyed by user
__device__ int2  g_csr_iu[NE_MAX];            // (user_col, val bits) keyed by item

__device__ int   g_ptr_u[N_USERS + 1];
__device__ int   g_ptr_i[N_ITEMS + 1];
__device__ int   g_next_u[N_USERS];
__device__ int   g_next_i[N_ITEMS];
__device__ int   g_aux[256];                  // per-block scan aggregates

// ---------------------------------------------------------------------------
// Kernel 1: fused init — fp32 -> fp16 embedding convert (layer 0 tables)
// and zero the histogram arrays. Thread roles by index range.
// ---------------------------------------------------------------------------
__global__ void k_init(const float4* __restrict__ emb_u,
                       const float4* __restrict__ emb_i) {
    const int nuf4 = NUF / 4;
    const int nif4 = NIF / 4;
    int t = blockIdx.x * blockDim.x + threadIdx.x;

    if (t < nuf4) {
        float4 v = emb_u[t];
        __half2* p = reinterpret_cast<__half2*>(g_u16[0]);
        p[2 * t]     = __floats2half2_rn(v.x, v.y);
        p[2 * t + 1] = __floats2half2_rn(v.z, v.w);
        return;
    }
    t -= nuf4;
    if (t < nif4) {
        float4 v = emb_i[t];
        __half2* p = reinterpret_cast<__half2*>(g_i16[0]);
        p[2 * t]     = __floats2half2_rn(v.x, v.y);
        p[2 * t + 1] = __floats2half2_rn(v.z, v.w);
        return;
    }
    t -= nif4;
    if (t <= N_USERS) { g_ptr_u[t] = 0; return; }
    t -= (N_USERS + 1);
    if (t <= N_ITEMS) { g_ptr_i[t] = 0; }
}

// ---------------------------------------------------------------------------
// Kernel 2: degree histogram
// ---------------------------------------------------------------------------
__global__ void k_hist(const int* __restrict__ edge_user,
                       const int* __restrict__ edge_item, int ne) {
    int t = blockIdx.x * blockDim.x + threadIdx.x;
    if (t >= ne) return;
    atomicAdd(&g_ptr_u[edge_user[t]], 1);
    atomicAdd(&g_ptr_i[edge_item[t]], 1);
}

// ---------------------------------------------------------------------------
// Kernel 3a: per-block aggregates of the concatenated [u | i] histogram.
// Spin-free: no inter-block dependencies.
// ---------------------------------------------------------------------------
__global__ void k_scanA() {
    int i = blockIdx.x * 1024 + threadIdx.x;
    int v = 0;
    if (i < N_USERS)    v = g_ptr_u[i];
    else if (i < NTOT)  v = g_ptr_i[i - N_USERS];

    #pragma unroll
    for (int off = 16; off > 0; off >>= 1)
        v += __shfl_xor_sync(0xffffffffu, v, off);

    __shared__ int ws[32];
    int warp = threadIdx.x >> 5;
    int lane = threadIdx.x & 31;
    if (lane == 0) ws[warp] = v;
    __syncthreads();
    if (threadIdx.x < 32) {
        int t = ws[threadIdx.x];
        #pragma unroll
        for (int off = 16; off > 0; off >>= 1)
            t += __shfl_xor_sync(0xffffffffu, t, off);
        if (threadIdx.x == 0) g_aux[blockIdx.x] = t;
    }
}

// ---------------------------------------------------------------------------
// Kernel 3b: each block redundantly scans the 147 aggregates, block-scans its
// own tile, and writes the final exclusive offsets (+ cursor copies + tails).
// The item part is rebased by -ne (sum of user counts == ne).
// ---------------------------------------------------------------------------
__global__ void k_scanB(int ne) {
    __shared__ int s[1024];
    __shared__ int aux_s[256];
    int b = blockIdx.x;
    int i = b * 1024 + threadIdx.x;

    if (threadIdx.x < 256)
        aux_s[threadIdx.x] = (threadIdx.x < SCAN_BLOCKS) ? g_aux[threadIdx.x] : 0;

    int v = 0;
    if (i < N_USERS)    v = g_ptr_u[i];
    else if (i < NTOT)  v = g_ptr_i[i - N_USERS];
    s[threadIdx.x] = v;
    __syncthreads();

    // inclusive scan of aggregates (256-wide, threads < 256 do the work)
    #pragma unroll
    for (int off = 1; off < 256; off <<= 1) {
        int t = 0;
        if (threadIdx.x < 256 && threadIdx.x >= off) t = aux_s[threadIdx.x - off];
        __syncthreads();
        if (threadIdx.x < 256) aux_s[threadIdx.x] += t;
        __syncthreads();
    }

    // inclusive scan of the tile
    #pragma unroll
    for (int off = 1; off < 1024; off <<= 1) {
        int t = (threadIdx.x >= off) ? s[threadIdx.x - off] : 0;
        __syncthreads();
        s[threadIdx.x] += t;
        __syncthreads();
    }

    int prefix = (b == 0) ? 0 : aux_s[b - 1];
    int fin = prefix + s[threadIdx.x] - v;   // exclusive

    if (i < N_USERS) {
        g_ptr_u[i] = fin;
        g_next_u[i] = fin;
    } else if (i < NTOT) {
        int j = i - N_USERS;
        int w = fin - ne;
        g_ptr_i[j] = w;
        g_next_i[j] = w;
    }
    if (i == 0) {
        g_ptr_u[N_USERS] = ne;
        g_ptr_i[N_ITEMS] = ne;
    }
}

// ---------------------------------------------------------------------------
// Kernel 4: scatter edges into both CSR structures
// ---------------------------------------------------------------------------
__global__ void k_build(const int* __restrict__ edge_user,
                        const int* __restrict__ edge_item,
                        const float* __restrict__ vals_ui,
                        const float* __restrict__ vals_iu, int ne) {
    int t = blockIdx.x * blockDim.x + threadIdx.x;
    if (t >= ne) return;
    int u = edge_user[t];
    int i = edge_item[t];
    int pu = atomicAdd(&g_next_u[u], 1);
    g_csr_ui[pu] = make_int2(i, __float_as_int(vals_ui[t]));
    int pi = atomicAdd(&g_next_i[i], 1);
    g_csr_iu[pi] = make_int2(u, __float_as_int(vals_iu[t]));
}

// ---------------------------------------------------------------------------
// Kernel 5: CSR SpMM (fp16 tables, fp32 accumulate), one warp per dest row.
// Lane layout: grp = lane>>3 (neighbor slot 0..3), sub = lane&7 (16B chunk).
// Each warp-load (LDG.128) fetches 4 neighbors' chunks at once:
// ~4 warp-instructions per edge instead of ~8.
// ---------------------------------------------------------------------------
__global__ void __launch_bounds__(256) k_spmm(const float* __restrict__ du,
                                              const float* __restrict__ di,
                                              int k) {
    __shared__ int2 stage[8][32];
    int warp = threadIdx.x >> 5;
    int lane = threadIdx.x & 31;
    int grp  = lane >> 3;     // 0..3: neighbor slot
    int sub  = lane & 7;      // 0..7: 16B chunk within the 128B row
    int row = blockIdx.x * 8 + warp;

    const int2* csr; const int* ptr;
    const uint4* src4; const uint4* prev4; const float* dvec;
    uint4* dst4; int r;

    if (row < N_USERS) {
        r = row; csr = g_csr_ui; ptr = g_ptr_u;
        src4  = reinterpret_cast<const uint4*>(g_i16[k - 1]);
        prev4 = reinterpret_cast<const uint4*>(g_u16[k - 1]);
        dvec = du;
        dst4  = reinterpret_cast<uint4*>(g_u16[k]);
    } else {
        r = row - N_USERS;
        if (r >= N_ITEMS) return;
        csr = g_csr_iu; ptr = g_ptr_i;
        src4  = reinterpret_cast<const uint4*>(g_u16[k - 1]);
        prev4 = reinterpret_cast<const uint4*>(g_i16[k - 1]);
        dvec = di;
        dst4  = reinterpret_cast<uint4*>(g_i16[k]);
    }

    int beg = ptr[r];
    int end = ptr[r + 1];

    float a0 = 0.f, a1 = 0.f, a2 = 0.f, a3 = 0.f;
    float a4 = 0.f, a5 = 0.f, a6 = 0.f, a7 = 0.f;

    for (int bb = beg; bb < end; bb += 32) {
        int n = min(32, end - bb);
        if (lane < n) stage[warp][lane] = csr[bb + lane];
        __syncwarp();

        int j = 0;
        // 8 edges per iteration: two LDG.128 in flight per warp
        for (; j + 8 <= n; j += 8) {
            int2 e0 = stage[warp][j + grp];
            int2 e1 = stage[warp][j + 4 + grp];
            uint4 q0 = src4[e0.x * 8 + sub];
            uint4 q1 = src4[e1.x * 8 + sub];
            float w0 = __int_as_float(e0.y);
            float w1 = __int_as_float(e1.y);
            {
                float2 f0 = __half22float2(*reinterpret_cast<__half2*>(&q0.x));
                float2 f1 = __half22float2(*reinterpret_cast<__half2*>(&q0.y));
                float2 f2 = __half22float2(*reinterpret_cast<__half2*>(&q0.z));
                float2 f3 = __half22float2(*reinterpret_cast<__half2*>(&q0.w));
                a0 = fmaf(w0, f0.x, a0); a1 = fmaf(w0, f0.y, a1);
                a2 = fmaf(w0, f1.x, a2); a3 = fmaf(w0, f1.y, a3);
                a4 = fmaf(w0, f2.x, a4); a5 = fmaf(w0, f2.y, a5);
                a6 = fmaf(w0, f3.x, a6); a7 = fmaf(w0, f3.y, a7);
            }
            {
                float2 f0 = __half22float2(*reinterpret_cast<__half2*>(&q1.x));
                float2 f1 = __half22float2(*reinterpret_cast<__half2*>(&q1.y));
                float2 f2 = __half22float2(*reinterpret_cast<__half2*>(&q1.z));
                float2 f3 = __half22float2(*reinterpret_cast<__half2*>(&q1.w));
                a0 = fmaf(w1, f0.x, a0); a1 = fmaf(w1, f0.y, a1);
                a2 = fmaf(w1, f1.x, a2); a3 = fmaf(w1, f1.y, a3);
                a4 = fmaf(w1, f2.x, a4); a5 = fmaf(w1, f2.y, a5);
                a6 = fmaf(w1, f3.x, a6); a7 = fmaf(w1, f3.y, a7);
            }
        }
        // tail: groups of 4 with weight-guard for the ragged end
        for (; j < n; j += 4) {
            int idx = j + grp;
            int2 e = stage[warp][idx < n ? idx : 0];
            float w = (idx < n) ? __int_as_float(e.y) : 0.f;
            uint4 q = src4[e.x * 8 + sub];
            float2 f0 = __half22float2(*reinterpret_cast<__half2*>(&q.x));
            float2 f1 = __half22float2(*reinterpret_cast<__half2*>(&q.y));
            float2 f2 = __half22float2(*reinterpret_cast<__half2*>(&q.z));
            float2 f3 = __half22float2(*reinterpret_cast<__half2*>(&q.w));
            a0 = fmaf(w, f0.x, a0); a1 = fmaf(w, f0.y, a1);
            a2 = fmaf(w, f1.x, a2); a3 = fmaf(w, f1.y, a3);
            a4 = fmaf(w, f2.x, a4); a5 = fmaf(w, f2.y, a5);
            a6 = fmaf(w, f3.x, a6); a7 = fmaf(w, f3.y, a7);
        }
        __syncwarp();
    }

    // reduce across the 4 neighbor groups (lanes differing in bits 3,4)
    #pragma unroll
    for (int off = 8; off <= 16; off <<= 1) {
        a0 += __shfl_xor_sync(0xffffffffu, a0, off);
        a1 += __shfl_xor_sync(0xffffffffu, a1, off);
        a2 += __shfl_xor_sync(0xffffffffu, a2, off);
        a3 += __shfl_xor_sync(0xffffffffu, a3, off);
        a4 += __shfl_xor_sync(0xffffffffu, a4, off);
        a5 += __shfl_xor_sync(0xffffffffu, a5, off);
        a6 += __shfl_xor_sync(0xffffffffu, a6, off);
        a7 += __shfl_xor_sync(0xffffffffu, a7, off);
    }

    // epilogue: lanes 0..7 add the diagonal term and store their 16B chunk
    if (grp == 0) {
        float dd = dvec[r];
        uint4 pq = prev4[r * 8 + sub];
        float2 p0 = __half22float2(*reinterpret_cast<__half2*>(&pq.x));
        float2 p1 = __half22float2(*reinterpret_cast<__half2*>(&pq.y));
        float2 p2 = __half22float2(*reinterpret_cast<__half2*>(&pq.z));
        float2 p3 = __half22float2(*reinterpret_cast<__half2*>(&pq.w));
        a0 = fmaf(dd, p0.x, a0); a1 = fmaf(dd, p0.y, a1);
        a2 = fmaf(dd, p1.x, a2); a3 = fmaf(dd, p1.y, a3);
        a4 = fmaf(dd, p2.x, a4); a5 = fmaf(dd, p2.y, a5);
        a6 = fmaf(dd, p3.x, a6); a7 = fmaf(dd, p3.y, a7);
        uint4 o;
        __half2 h;
        h = __floats2half2_rn(a0, a1); o.x = *reinterpret_cast<unsigned*>(&h);
        h = __floats2half2_rn(a2, a3); o.y = *reinterpret_cast<unsigned*>(&h);
        h = __floats2half2_rn(a4, a5); o.z = *reinterpret_cast<unsigned*>(&h);
        h = __floats2half2_rn(a6, a7); o.w = *reinterpret_cast<unsigned*>(&h);
        dst4[r * 8 + sub] = o;
    }
}

// ---------------------------------------------------------------------------
// Kernel 6: output gather. out layout [seg(3)][batch][256], fp32.
// ---------------------------------------------------------------------------
__global__ void k_out_gather(const int* __restrict__ users,
                             const int* __restrict__ pos_item,
                             const int* __restrict__ neg_item,
                             const float* __restrict__ emb_user,
                             const float* __restrict__ emb_item,
                             float4* __restrict__ out, int batch) {
    int t = blockIdx.x * blockDim.x + threadIdx.x;
    int total = 3 * batch * 64;
    if (t >= total) return;

    int q   = t & 63;
    int b   = (t >> 6) % batch;
    int seg = t / (batch * 64);
    int k   = q >> 4;
    int f4  = q & 15;

    int row;
    bool is_user = (seg == 0);
    if (is_user)        row = users[b];
    else if (seg == 1)  row = pos_item[b];
    else                row = neg_item[b];

    if (k == 0) {
        const float* tab = is_user ? emb_user : emb_item;
        out[t] = *reinterpret_cast<const float4*>(tab + (size_t)row * FDIM + f4 * 4);
    } else {
        const __half* tab = is_user ? g_u16[k] : g_i16[k];
        uint2 raw = *reinterpret_cast<const uint2*>(tab + (size_t)row * FDIM + f4 * 4);
        __half2 h0 = *reinterpret_cast<const __half2*>(&raw.x);
        __half2 h1 = *reinterpret_cast<const __half2*>(&raw.y);
        float2 a = __half22float2(h0);
        float2 c = __half22float2(h1);
        out[t] = make_float4(a.x, a.y, c.x, c.y);
    }
}

// ---------------------------------------------------------------------------
// kernel_launch: 9 launches; launch index 5 (ncu -s 5 -c 1) = spmm layer 1
// ---------------------------------------------------------------------------
extern "C" void kernel_launch(void* const* d_in, const int* in_sizes, int n_in,
                              void* d_out, int out_size) {
    const int*   edge_user = (const int*)  d_in[0];
    const int*   edge_item = (const int*)  d_in[1];
    const float* vals_ui   = (const float*)d_in[2];
    const float* vals_iu   = (const float*)d_in[3];
    const float* d_users   = (const float*)d_in[4];
    const float* d_items   = (const float*)d_in[5];
    const float* emb_user  = (const float*)d_in[6];
    const float* emb_item  = (const float*)d_in[7];
    const int*   users     = (const int*)  d_in[8];
    const int*   pos_item  = (const int*)  d_in[9];
    const int*   neg_item  = (const int*)  d_in[10];

    const int ne    = in_sizes[0];
    const int batch = in_sizes[8];
    const int TPB   = 256;

    // 0) convert embeddings + zero histograms
    {
        int total = NUF / 4 + NIF / 4 + (N_USERS + 1) + (N_ITEMS + 1);
        k_init<<<(total + TPB - 1) / TPB, TPB>>>(
            (const float4*)emb_user, (const float4*)emb_item);
    }
    // 1) histogram
    k_hist<<<(ne + TPB - 1) / TPB, TPB>>>(edge_user, edge_item, ne);
    // 2-3) spin-free two-phase scan
    k_scanA<<<SCAN_BLOCKS, 1024>>>();
    k_scanB<<<SCAN_BLOCKS, 1024>>>(ne);
    // 4) CSR scatter
    k_build<<<(ne + TPB - 1) / TPB, TPB>>>(edge_user, edge_item, vals_ui, vals_iu, ne);

    // 5-7) 3 layers of fused SpMM + diagonal
    int spmm_blocks = (N_USERS + N_ITEMS + 7) / 8;
    for (int k = 1; k <= N_LAYERS; k++) {
        k_spmm<<<spmm_blocks, TPB>>>(d_users, d_items, k);
    }

    // 8) output gather
    int total = 3 * batch * 64;
    k_out_gather<<<(total + TPB - 1) / TPB, TPB>>>(
        users, pos_item, neg_item, emb_user, emb_item, (float4*)d_out, batch);
}